// round 6
// baseline (speedup 1.0000x reference)
#include <cuda_runtime.h>
#include <cuda_bf16.h>

// Shapes (fixed by the problem): knn_x_w [B=8, C=256, N=2048, K=24] f32.
// Key identity: e_x in the reference is a per-row scalar ([B,C,N,1]), so
//   up/down = (mean_k(x)*e_x)/e_x = mean_k(x)  ==> _k_anp(x) == mean_k(x).
// The p / std / log1p machinery cancels exactly. Hence
//   lc_x = _k_anp(x) + mean_k(x) = 2*mean_k(x) = sum_k(x) / 12.
#define B_ 8
#define C_ 256
#define N_ 2048
#define K_ 24
#define BC_ (B_ * C_)          // 2048 blocks in both passes
#define ROWS_PER_CH (B_ * N_)  // 16384 values per channel for BN stats

// Per-(b,c)-block partial sums for batchnorm stats (deterministic: no atomics).
__device__ float g_psum[BC_];
__device__ float g_psumsq[BC_];

// ---------------------------------------------------------------------------
// Pass 1: per-row K-reduction -> lc = sum_k / 12, write lc into out (scratch),
// and per-block partial (sum, sumsq) for the channel stats.
// One block per (b,c): reads a contiguous 196 KB slab (2048 rows x 24 f32).
// Input loads use __ldcs (evict-first): the 402 MB input is single-use, while
// the 16.8 MB lc buffer must stay L2-resident for pass 2.
// Two rows per thread-iteration: 12 independent LDG.128 front-batched (MLP~12)
// to hide DRAM latency per the B300 3-term LDG model.
// ---------------------------------------------------------------------------
__global__ __launch_bounds__(256, 8)
void pool_pass1(const float* __restrict__ in, float* __restrict__ lc)
{
    const int bc = blockIdx.x;               // b*C + c
    const float4* __restrict__ base =
        reinterpret_cast<const float4*>(in) + (size_t)bc * (N_ * K_ / 4);
    float* __restrict__ lc_row = lc + (size_t)bc * N_;

    float s = 0.f, s2 = 0.f;

    // 2048 rows / 256 threads = 8 rows/thread = 4 double-row iterations.
    for (int n = threadIdx.x; n < N_; n += 512) {
        const int n2 = n + 256;
        const float4* pa = base + n  * 6;
        const float4* pb = base + n2 * 6;

        float4 va[6], vb[6];
        #pragma unroll
        for (int i = 0; i < 6; ++i) va[i] = __ldcs(pa + i);
        #pragma unroll
        for (int i = 0; i < 6; ++i) vb[i] = __ldcs(pb + i);

        float acc_a = 0.f, acc_b = 0.f;
        #pragma unroll
        for (int i = 0; i < 6; ++i) acc_a += (va[i].x + va[i].y) + (va[i].z + va[i].w);
        #pragma unroll
        for (int i = 0; i < 6; ++i) acc_b += (vb[i].x + vb[i].y) + (vb[i].z + vb[i].w);

        float la = acc_a * (1.0f / 12.0f);   // 2 * mean over K=24
        float lb = acc_b * (1.0f / 12.0f);
        lc_row[n]  = la;
        lc_row[n2] = lb;
        s  += la + lb;
        s2 += la * la + lb * lb;
    }

    // Block reduction (8 warps x 32 lanes).
    __shared__ float sh_s[8], sh_s2[8];
    #pragma unroll
    for (int o = 16; o > 0; o >>= 1) {
        s  += __shfl_down_sync(0xffffffffu, s,  o);
        s2 += __shfl_down_sync(0xffffffffu, s2, o);
    }
    const int warp = threadIdx.x >> 5;
    const int lane = threadIdx.x & 31;
    if (lane == 0) { sh_s[warp] = s; sh_s2[warp] = s2; }
    __syncthreads();
    if (warp == 0) {
        s  = (lane < 8) ? sh_s[lane]  : 0.f;
        s2 = (lane < 8) ? sh_s2[lane] : 0.f;
        #pragma unroll
        for (int o = 4; o > 0; o >>= 1) {
            s  += __shfl_down_sync(0xffffffffu, s,  o);
            s2 += __shfl_down_sync(0xffffffffu, s2, o);
        }
        if (lane == 0) { g_psum[bc] = s; g_psumsq[bc] = s2; }
    }
}

// ---------------------------------------------------------------------------
// Pass 2: per-channel BN (training stats, biased var) + exact GELU, in-place
// on the lc buffer (= d_out). One block per (b,c), 512 float4 each.
// lc should be L2-resident after pass 1 (input was streamed with evict-first).
// ---------------------------------------------------------------------------
__global__ __launch_bounds__(256, 16)
void pool_pass2(float* __restrict__ io,
                const float* __restrict__ gamma,
                const float* __restrict__ beta)
{
    const int bc = blockIdx.x;
    const int c  = bc & (C_ - 1);

    // Sum the 8 per-b partials for this channel (deterministic order).
    float s = 0.f, s2 = 0.f;
    #pragma unroll
    for (int b = 0; b < B_; ++b) {
        s  += g_psum[b * C_ + c];
        s2 += g_psumsq[b * C_ + c];
    }
    const float mean = s  * (1.0f / ROWS_PER_CH);
    const float var  = s2 * (1.0f / ROWS_PER_CH) - mean * mean;  // biased
    const float inv  = rsqrtf(var + 1e-5f);
    const float gsc  = gamma[c] * inv;
    const float bsc  = beta[c] - mean * gsc;   // y = v*gsc + bsc

    float4* p = reinterpret_cast<float4*>(io) + (size_t)bc * (N_ / 4);

    #pragma unroll 2
    for (int i = threadIdx.x; i < N_ / 4; i += 256) {
        float4 v = p[i];
        float y;
        y = v.x * gsc + bsc; v.x = 0.5f * y * (1.f + erff(y * 0.70710678118654752f));
        y = v.y * gsc + bsc; v.y = 0.5f * y * (1.f + erff(y * 0.70710678118654752f));
        y = v.z * gsc + bsc; v.z = 0.5f * y * (1.f + erff(y * 0.70710678118654752f));
        y = v.w * gsc + bsc; v.w = 0.5f * y * (1.f + erff(y * 0.70710678118654752f));
        p[i] = v;
    }
}

extern "C" void kernel_launch(void* const* d_in, const int* in_sizes, int n_in,
                              void* d_out, int out_size)
{
    const float* knn  = (const float*)d_in[0];   // [8,256,2048,24]
    const float* gma  = (const float*)d_in[1];   // [256]
    const float* bta  = (const float*)d_in[2];   // [256]
    float* out = (float*)d_out;                  // [8,256,2048]

    pool_pass1<<<BC_, 256>>>(knn, out);
    pool_pass2<<<BC_, 256>>>(out, gma, bta);
}

// round 12
// speedup vs baseline: 1.0808x; 1.0808x over previous
#include <cuda_runtime.h>
#include <cuda_bf16.h>

// knn_x_w [B=8, C=256, N=2048, K=24] f32.
// Identity: e_x is a per-row scalar => _k_anp(x) == mean_k(x) exactly;
// lc_x = 2*mean_k(x) = sum_k(x)/12.
#define B_ 8
#define C_ 256
#define N_ 2048
#define K_ 24
#define BC_ (B_ * C_)
#define QUARTERS 4                 // 512-row work items for wave-quantization fix
#define ITEMS (BC_ * QUARTERS)     // 8192 pass-1 blocks -> 6.92 waves @ occ 8
#define ROWS_PER_CH (B_ * N_)      // 16384 values per channel for BN stats

// Per-item partial sums for batchnorm stats (deterministic: no atomics).
__device__ float g_psum[ITEMS];
__device__ float g_psumsq[ITEMS];

// ---------------------------------------------------------------------------
// Pass 1: per-row K-reduction -> lc = sum_k/12 into out (scratch) + per-item
// (sum, sumsq). One block per quarter-slab (512 rows x 24 f32 = 48 KB read).
// 8192 blocks @ occ 8 -> 6.92 waves (98.9% fill vs 86.5% at 2048 blocks).
// 12 front-batched LDG.128/thread (__ldcs: input is single-use; keep lc in L2).
// ---------------------------------------------------------------------------
__global__ __launch_bounds__(256, 8)
void pool_pass1(const float* __restrict__ in, float* __restrict__ lc)
{
    const int m  = blockIdx.x;           // 0..8191
    const int bc = m >> 2;
    const int q  = m & 3;
    const float4* __restrict__ base =
        reinterpret_cast<const float4*>(in) + (size_t)bc * (N_ * K_ / 4) + q * (512 * K_ / 4);
    float* __restrict__ lcp = lc + (size_t)bc * N_ + q * 512;

    const int n = threadIdx.x;           // rows n and n+256 of this 512-row item
    const float4* pa = base + n * 6;
    const float4* pb = base + (n + 256) * 6;

    float4 va[6], vb[6];
    #pragma unroll
    for (int i = 0; i < 6; ++i) va[i] = __ldcs(pa + i);
    #pragma unroll
    for (int i = 0; i < 6; ++i) vb[i] = __ldcs(pb + i);

    float acc_a = 0.f, acc_b = 0.f;
    #pragma unroll
    for (int i = 0; i < 6; ++i) acc_a += (va[i].x + va[i].y) + (va[i].z + va[i].w);
    #pragma unroll
    for (int i = 0; i < 6; ++i) acc_b += (vb[i].x + vb[i].y) + (vb[i].z + vb[i].w);

    const float la = acc_a * (1.0f / 12.0f);
    const float lb = acc_b * (1.0f / 12.0f);
    lcp[n]       = la;
    lcp[n + 256] = lb;

    float s  = la + lb;
    float s2 = la * la + lb * lb;

    // Block reduction (8 warps x 32 lanes) -> per-item partials.
    __shared__ float sh_s[8], sh_s2[8];
    #pragma unroll
    for (int o = 16; o > 0; o >>= 1) {
        s  += __shfl_down_sync(0xffffffffu, s,  o);
        s2 += __shfl_down_sync(0xffffffffu, s2, o);
    }
    const int warp = threadIdx.x >> 5;
    const int lane = threadIdx.x & 31;
    if (lane == 0) { sh_s[warp] = s; sh_s2[warp] = s2; }
    __syncthreads();
    if (warp == 0) {
        s  = (lane < 8) ? sh_s[lane]  : 0.f;
        s2 = (lane < 8) ? sh_s2[lane] : 0.f;
        #pragma unroll
        for (int o = 4; o > 0; o >>= 1) {
            s  += __shfl_down_sync(0xffffffffu, s,  o);
            s2 += __shfl_down_sync(0xffffffffu, s2, o);
        }
        if (lane == 0) { g_psum[m] = s; g_psumsq[m] = s2; }
    }
}

// Branchless exact-GELU: Abramowitz-Stegun 7.1.26 erf (|abs err| <= 1.5e-7),
// odd symmetry via copysign. ~15 instrs, 2 MUFU (rcp-approx, ex2) vs the
// long branchy builtin erff. Output abs error ~1e-7 -> negligible vs 1e-3 gate.
__device__ __forceinline__ float gelu_f(float y)
{
    float z = fabsf(y) * 0.70710678118654752f;
    float t = __fdividef(1.0f, fmaf(0.3275911f, z, 1.0f));   // MUFU.RCP path
    float p = fmaf(1.061405429f, t, -1.453152027f);
    p = fmaf(p, t, 1.421413741f);
    p = fmaf(p, t, -0.284496736f);
    p = fmaf(p, t, 0.254829592f);
    p *= t;
    float e    = __expf(-z * z);
    float erfa = fmaf(-p, e, 1.0f);            // erf(|z|) in [0,1)
    return 0.5f * y * (1.0f + copysignf(erfa, y));
}

// ---------------------------------------------------------------------------
// Pass 2: per-channel BN + GELU in-place on lc (= d_out).
// One block per (b,c); warp 0 reduces this channel's 32 partials once and
// broadcasts scale/bias through smem (was: 16 redundant loads per thread).
// Block 128, 4 front-batched float4 per thread (MLP 4) to cover L2 latency.
// ---------------------------------------------------------------------------
__global__ __launch_bounds__(128, 16)
void pool_pass2(float* __restrict__ io,
                const float* __restrict__ gamma,
                const float* __restrict__ beta)
{
    const int bc = blockIdx.x;
    const int c  = bc & (C_ - 1);

    __shared__ float sh_gsc, sh_bsc;
    if (threadIdx.x < 32) {
        // 32 partials for channel c: b = lane>>2, quarter = lane&3.
        const int b   = threadIdx.x >> 2;
        const int qq  = threadIdx.x & 3;
        const int idx = (((b << 8) | c) << 2) | qq;
        float s  = g_psum[idx];
        float s2 = g_psumsq[idx];
        #pragma unroll
        for (int o = 16; o > 0; o >>= 1) {
            s  += __shfl_down_sync(0xffffffffu, s,  o);
            s2 += __shfl_down_sync(0xffffffffu, s2, o);
        }
        if (threadIdx.x == 0) {
            const float mean = s  * (1.0f / ROWS_PER_CH);
            const float var  = s2 * (1.0f / ROWS_PER_CH) - mean * mean;  // biased
            const float inv  = rsqrtf(var + 1e-5f);
            const float gsc  = gamma[c] * inv;
            sh_gsc = gsc;
            sh_bsc = beta[c] - mean * gsc;
        }
    }
    __syncthreads();
    const float gsc = sh_gsc;
    const float bsc = sh_bsc;

    float4* p = reinterpret_cast<float4*>(io) + (size_t)bc * (N_ / 4);

    float4 v[4];
    #pragma unroll
    for (int j = 0; j < 4; ++j) v[j] = p[threadIdx.x + j * 128];
    #pragma unroll
    for (int j = 0; j < 4; ++j) {
        v[j].x = gelu_f(fmaf(v[j].x, gsc, bsc));
        v[j].y = gelu_f(fmaf(v[j].y, gsc, bsc));
        v[j].z = gelu_f(fmaf(v[j].z, gsc, bsc));
        v[j].w = gelu_f(fmaf(v[j].w, gsc, bsc));
    }
    #pragma unroll
    for (int j = 0; j < 4; ++j) p[threadIdx.x + j * 128] = v[j];
}

extern "C" void kernel_launch(void* const* d_in, const int* in_sizes, int n_in,
                              void* d_out, int out_size)
{
    const float* knn  = (const float*)d_in[0];   // [8,256,2048,24]
    const float* gma  = (const float*)d_in[1];   // [256]
    const float* bta  = (const float*)d_in[2];   // [256]
    float* out = (float*)d_out;                  // [8,256,2048]

    pool_pass1<<<ITEMS, 256>>>(knn, out);
    pool_pass2<<<BC_, 128>>>(out, gma, bta);
}